// round 11
// baseline (speedup 1.0000x reference)
#include <cuda_runtime.h>
#include <math.h>

// NeuralstackOnly: differentiable stack + latch scan.
// One CTA per batch (B=32). 512 threads, 4 V-lanes per thread (V=2048).
// Per step: one block barrier; reductions pipelined one step ahead;
// pointer math in one warp; stack/top math in packed fma.rn.f32x2.
// ~110 regs/thread (no spills). Phase C FMA floor ~576 cyc/step/SM.

#define THREADS 512
#define NWARP   (THREADS / 32)   // 16
#define VPT     4                // V elements per thread
#define NPACK   (VPT / 2)        // f32x2 packs per thread
#define VDIM    2048
#define NSTK    12
#define EPSF    1e-8f
#define ZOFF    0.001f

typedef unsigned long long u64;

__device__ __forceinline__ u64 f2pack(float a, float b) {
    u64 r; asm("mov.b64 %0, {%1, %2};" : "=l"(r) : "f"(a), "f"(b)); return r;
}
__device__ __forceinline__ u64 f2bcast(float a) {
    u64 r; asm("mov.b64 %0, {%1, %1};" : "=l"(r) : "f"(a)); return r;
}
__device__ __forceinline__ void f2unpack(u64 v, float& a, float& b) {
    asm("mov.b64 {%0, %1}, %2;" : "=f"(a), "=f"(b) : "l"(v));
}
__device__ __forceinline__ u64 f2fma(u64 a, u64 b, u64 c) {
    u64 d; asm("fma.rn.f32x2 %0, %1, %2, %3;" : "=l"(d) : "l"(a), "l"(b), "l"(c)); return d;
}

__device__ __forceinline__ float wredsum(float v) {
#pragma unroll
    for (int m = 16; m > 0; m >>= 1) v += __shfl_xor_sync(0xffffffffu, v, m);
    return v;
}

__device__ __forceinline__ void load4(float* d, const float* p) {
    float4 a = *(const float4*)p;
    d[0] = a.x; d[1] = a.y; d[2] = a.z; d[3] = a.w;
}
__device__ __forceinline__ void store4(float* p, const float* d) {
    *(float4*)p = make_float4(d[0], d[1], d[2], d[3]);
}

__global__ void __launch_bounds__(THREADS, 1)
neuralstack_kernel(const float* __restrict__ x,
                   const float* __restrict__ sp,
                   const float* __restrict__ sharp_ptr,
                   const float* __restrict__ le,
                   const float* __restrict__ latch0,
                   float* __restrict__ out,
                   int B, int T)
{
    const int b    = blockIdx.x;
    const int tid  = threadIdx.x;
    const int wid  = tid >> 5;
    const int lane = tid & 31;
    const int base = tid * VPT;
    const int LASTW = NWARP - 1;

    __shared__ float4 pbuf[2][NWARP];   // per-warp reduction partials, double-buffered
    __shared__ float4 abuf[2][NSTK];    // (alpha, beta, gamma, new_ptr) per stack slot
    __shared__ float2 nbuf[NWARP];      // prologue: ||sp||^2, ||le||^2 partials

    const float sharp = sharp_ptr[0];
    const bool  fast5 = (sharp == 5.0f);

    float spv[VPT], lev[VPT], lat[VPT];
    float xa[VPT], xb[VPT], xc[VPT];    // x_t, x_{t+1}, x_{t+2}

    load4(spv, sp + base);
    load4(lev, le + base);
    load4(lat, latch0 + (size_t)b * VDIM + base);
    const float* xrow = x + (size_t)b * T * VDIM + base;
    load4(xa, xrow);
#pragma unroll
    for (int j = 0; j < VPT; j++) { xb[j] = 0.f; xc[j] = 0.f; }
    if (T > 1) load4(xb, xrow + VDIM);

    // ---- prologue: reductions for t=0 (uses latch0, x_0) + constant norms ----
    {
        float p0 = 0, p1 = 0, p2 = 0, p3 = 0, p4 = 0, p5 = 0;
#pragma unroll
        for (int j = 0; j < VPT; j++) {
            p0 += lat[j] * spv[j];
            p1 += lat[j] * lat[j];
            p2 += xa[j] * lev[j];
            p3 += xa[j] * xa[j];
            p4 += spv[j] * spv[j];
            p5 += lev[j] * lev[j];
        }
        p0 = wredsum(p0); p1 = wredsum(p1); p2 = wredsum(p2);
        p3 = wredsum(p3); p4 = wredsum(p4); p5 = wredsum(p5);
        if (lane == 0) {
            pbuf[0][wid] = make_float4(p0, p1, p2, p3);
            nbuf[wid]    = make_float2(p4, p5);
        }
    }
    float ptrreg = 0.f;
    if (wid == LASTW) ptrreg = (lane == 0) ? 1.f : 0.f;
    __syncthreads();

    float ssp = 0.f, sle = 0.f;
#pragma unroll
    for (int w = 0; w < NWARP; w++) { float2 q = nbuf[w]; ssp += q.x; sle += q.y; }
    const float nsp = fmaxf(sqrtf(ssp), EPSF);
    const float nle = fmaxf(sqrtf(sle), EPSF);

    // stack state: packed f32x2, initialized to ZERO_OFFSET
    u64 s2[NSTK][NPACK];
    {
        const u64 zi = f2bcast(ZOFF);
#pragma unroll
        for (int n = 0; n < NSTK; n++)
#pragma unroll
            for (int k = 0; k < NPACK; k++) s2[n][k] = zi;
    }

    // output layout: [outs | latches | pops | tops] tuple concatenation
    const size_t BTV = (size_t)B * T * VDIM;
    float* outs_p  = out + (size_t)b * T * VDIM + base;
    float* latch_p = out + BTV + (size_t)b * T * VDIM + base;
    float* pops_p  = out + 2 * BTV + (size_t)b * T;
    float* tops_p  = out + 2 * BTV + (size_t)B * T + (size_t)b * T * VDIM + base;
    const float* xpf = xrow + 2 * (size_t)VDIM;   // prefetch cursor (x_{t+2})

    for (int t = 0; t < T; ++t) {
        const int par = t & 1;

        // ---- Phase A: finish cross-warp sums, compute pop/interp, update latch ----
        float r0 = 0, r1 = 0, r2 = 0, r3 = 0;
#pragma unroll
        for (int w = 0; w < NWARP; w++) {
            float4 q = pbuf[par][w];
            r0 += q.x; r1 += q.y; r2 += q.z; r3 += q.w;
        }
        const float nl  = fmaxf(sqrtf(r1), EPSF);
        const float cs  = r0 / (nsp * nl);
        const float pop  = (cs > 0.f) ? cs : expm1f(cs);   // jax.nn.elu
        const float push = 1.f - pop;
        const float nx     = fmaxf(sqrtf(r3), EPSF);
        const float interp = r2 / (nle * nx);
        const float oim    = 1.f - interp;
#pragma unroll
        for (int j = 0; j < VPT; j++) lat[j] = oim * lat[j] + interp * xa[j];
        store4(latch_p, lat);
        if (tid == 0) pops_p[t] = pop;

        // ---- Phase B: prefetch x_{t+2}; reductions for step t+1; ptr math in last warp ----
        if (t + 2 < T) load4(xc, xpf);

        float q0 = 0, q1 = 0, q2 = 0, q3 = 0;
#pragma unroll
        for (int j = 0; j < VPT; j++) {
            q0 += lat[j] * spv[j];
            q1 += lat[j] * lat[j];
            q2 += xb[j] * lev[j];
            q3 += xb[j] * xb[j];
        }
        q0 = wredsum(q0); q1 = wredsum(q1); q2 = wredsum(q2); q3 = wredsum(q3);
        if (lane == 0) pbuf[par ^ 1][wid] = make_float4(q0, q1, q2, q3);

        if (wid == LASTW) {
            const float pv = ptrreg;                                          // ptr_{t-1}[lane]
            const float pp = __shfl_sync(0xffffffffu, pv, (lane + 11) % 12);  // roll +1
            const float pq = __shfl_sync(0xffffffffu, pv, (lane + 1) % 12);   // roll -1
            const float mix = push * pp + pop * pq;
            const float m   = fmaxf(mix, 0.f);
            float pw;
            if (fast5) { float m2 = m * m; pw = m2 * m2 * m; }
            else       { pw = powf(m, sharp); }
            const float pz   = (lane < NSTK) ? pw : 0.f;
            const float ssum = wredsum(pz);
            const float np   = pw / (ssum + EPSF);
            const float al = push * (1.f - pp) + pop * (1.f - pv);
            const float be = push * pp;
            const float ga = pop * ZOFF * pv;
            if (lane < NSTK) abuf[par][lane] = make_float4(al, be, ga, np);
            ptrreg = np;
        }
        __syncthreads();

        // ---- Phase C: stack update + top readout (packed fma.rn.f32x2) ----
        u64 x2[NPACK], top2[NPACK];
#pragma unroll
        for (int k = 0; k < NPACK; k++) {
            x2[k]   = f2pack(xa[2 * k], xa[2 * k + 1]);
            top2[k] = 0ull;                                  // (0.f, 0.f)
        }
#pragma unroll
        for (int n = 0; n < NSTK; n++) {
            const float4 cf = abuf[par][n];
            const u64 a2 = f2bcast(cf.x);
            const u64 b2 = f2bcast(cf.y);
            const u64 g2 = f2bcast(cf.z);
            const u64 p2 = f2bcast(cf.w);
#pragma unroll
            for (int k = 0; k < NPACK; k++) {
                s2[n][k] = f2fma(a2, s2[n][k], f2fma(b2, x2[k], g2));
                top2[k]  = f2fma(p2, s2[n][k], top2[k]);
            }
        }
        float tv[VPT], ov[VPT];
#pragma unroll
        for (int k = 0; k < NPACK; k++) f2unpack(top2[k], tv[2 * k], tv[2 * k + 1]);
#pragma unroll
        for (int j = 0; j < VPT; j++) ov[j] = pop * tv[j];
        store4(tops_p, tv);
        store4(outs_p, ov);

        // rotate prefetch regs, advance row pointers
#pragma unroll
        for (int j = 0; j < VPT; j++) { xa[j] = xb[j]; xb[j] = xc[j]; }
        outs_p += VDIM; latch_p += VDIM; tops_p += VDIM; xpf += VDIM;
    }
}

extern "C" void kernel_launch(void* const* d_in, const int* in_sizes, int n_in,
                              void* d_out, int out_size)
{
    const float* x     = (const float*)d_in[0];   // [B,T,V]
    const float* sp    = (const float*)d_in[1];   // [V]
    const float* sharp = (const float*)d_in[2];   // [1]
    const float* le    = (const float*)d_in[3];   // [V]
    const float* l0    = (const float*)d_in[4];   // [B,V]

    const int V = in_sizes[1];                    // 2048
    const int B = in_sizes[4] / V;                // 32
    const int T = in_sizes[0] / (B * V);          // 256
    (void)n_in; (void)out_size;

    neuralstack_kernel<<<B, THREADS>>>(x, sp, sharp, le, l0, (float*)d_out, B, T);
}